// round 14
// baseline (speedup 1.0000x reference)
#include <cuda_runtime.h>
#include <cuda_bf16.h>
#include <math.h>
#include <cstdint>

// Problem constants
#define B_    4
#define N_    4096
#define E_    1024
#define H_    16
#define MTOT  16384        // B*N
#define EPSN  1e-4f
#define SCALE 2.0f         // H^0.25
#define FSCALE 0.125f      // PD^-0.5

// ---------------------------------------------------------------------------
// Scratch (device globals: allocation-free rule)
// ---------------------------------------------------------------------------
__device__ float g_q [16777216];     // (B,N,E) q proj fp32
__device__ float g_k [16777216];     // (B,N,E) k proj fp32
__device__ float g_v [16777216];     // (B,N,E) v proj fp32
__device__ float g_kvp[8388608];     // per block partial kv (128x64), 1024 blocks
__device__ float g_kv [524288];      // per bh kv (128x64)
__device__ __nv_bfloat16 g_xhi [16777216];
__device__ __nv_bfloat16 g_xlo [16777216];
__device__ __nv_bfloat16 g_aohi[16777216];
__device__ __nv_bfloat16 g_aolo[16777216];
__device__ __nv_bfloat16 g_whi [4194304];   // 4 x 1024x1024
__device__ __nv_bfloat16 g_wlo [4194304];

__device__ __forceinline__ float* sel_buf(int s) {
    return s == 0 ? g_q : (s == 1 ? g_k : g_v);
}

// ---------------------------------------------------------------------------
// PTX helpers (base-target sm_103 safe: mma.sync / ldmatrix / cp.async only)
// ---------------------------------------------------------------------------
__device__ __forceinline__ uint32_t smem_u32(const void* p) {
    uint32_t a;
    asm("{ .reg .u64 t; cvta.to.shared.u64 t, %1; cvt.u32.u64 %0, t; }"
        : "=r"(a) : "l"(p));
    return a;
}
__device__ __forceinline__ void cpasync16(uint32_t dst, const void* src) {
    asm volatile("cp.async.cg.shared.global [%0], [%1], 16;" :: "r"(dst), "l"(src));
}
#define CP_COMMIT()  asm volatile("cp.async.commit_group;" ::: "memory")
#define CP_WAIT(n)   asm volatile("cp.async.wait_group %0;" :: "n"(n) : "memory")

__device__ __forceinline__ void ldsm4(uint32_t* r, uint32_t addr) {
    asm volatile("ldmatrix.sync.aligned.m8n8.x4.shared.b16 {%0,%1,%2,%3}, [%4];"
                 : "=r"(r[0]), "=r"(r[1]), "=r"(r[2]), "=r"(r[3]) : "r"(addr));
}
__device__ __forceinline__ void mma16816(float* d, const uint32_t* a, const uint32_t* b) {
    asm volatile(
        "mma.sync.aligned.m16n8k16.row.col.f32.bf16.bf16.f32 "
        "{%0,%1,%2,%3}, {%4,%5,%6,%7}, {%8,%9}, {%0,%1,%2,%3};"
        : "+f"(d[0]), "+f"(d[1]), "+f"(d[2]), "+f"(d[3])
        : "r"(a[0]), "r"(a[1]), "r"(a[2]), "r"(a[3]), "r"(b[0]), "r"(b[1]));
}

// ---------------------------------------------------------------------------
// Split conversions: fp32 -> bf16 hi + bf16 lo.
// ---------------------------------------------------------------------------
__device__ __forceinline__ void split_store(const float4 v, __nv_bfloat16* hi,
                                            __nv_bfloat16* lo, int i)
{
    __nv_bfloat16 h0 = __float2bfloat16(v.x);
    __nv_bfloat16 h1 = __float2bfloat16(v.y);
    __nv_bfloat16 h2 = __float2bfloat16(v.z);
    __nv_bfloat16 h3 = __float2bfloat16(v.w);
    __nv_bfloat162* hp = (__nv_bfloat162*)hi;
    __nv_bfloat162* lp = (__nv_bfloat162*)lo;
    hp[i * 2]     = __nv_bfloat162(h0, h1);
    hp[i * 2 + 1] = __nv_bfloat162(h2, h3);
    lp[i * 2]     = __nv_bfloat162(__float2bfloat16(v.x - __bfloat162float(h0)),
                                   __float2bfloat16(v.y - __bfloat162float(h1)));
    lp[i * 2 + 1] = __nv_bfloat162(__float2bfloat16(v.z - __bfloat162float(h2)),
                                   __float2bfloat16(v.w - __bfloat162float(h3)));
}

__global__ __launch_bounds__(256) void conv_x(const float* __restrict__ src)
{
    int i = blockIdx.x * 256 + threadIdx.x;
    split_store(((const float4*)src)[i], g_xhi, g_xlo, i);
}

__global__ __launch_bounds__(256) void conv_w(
    const float* __restrict__ w0, const float* __restrict__ w1,
    const float* __restrict__ w2, const float* __restrict__ w3)
{
    int z = blockIdx.y;
    const float* src = z == 0 ? w0 : (z == 1 ? w1 : (z == 2 ? w2 : w3));
    int i = blockIdx.x * 256 + threadIdx.x;
    split_store(((const float4*)src)[i],
                g_whi + (size_t)z * 1048576, g_wlo + (size_t)z * 1048576, i);
}

// ---------------------------------------------------------------------------
// Tensor-core GEMM (NT) via mma.sync bf16 split:
// Y[16384,1024] = X @ W^T + bias.  grid (4, 128, nz); z selects W/bias/dst.
// 128x256 block, K-chunk 32, 256 thr (2x4 warps, 64x64 warp tile),
// 3-stage cp.async pipeline; MMA issue in 3 split-passes so adjacent MMAs
// never share an accumulator (breaks HMMA RAW chains).
// ---------------------------------------------------------------------------
#define A_TILE_B 10240     // 128 rows * 80 bytes
#define B_TILE_B 20480     // 256 rows * 80 bytes
#define STAGE_B  61440     // Ahi|Alo|Bhi|Blo
#define NSTAGE   3
__global__ __launch_bounds__(256, 1) void gemm_mma(
    int xsel, int wsel_base,
    const float* __restrict__ bias0, const float* __restrict__ bias1,
    const float* __restrict__ bias2,
    float* __restrict__ Yext, int ysel_base)
{
    const int z = blockIdx.z;
    const int wsel = wsel_base + z;
    const float* bias = z == 0 ? bias0 : (z == 1 ? bias1 : bias2);
    const __nv_bfloat16* Xhi = xsel ? g_aohi : g_xhi;
    const __nv_bfloat16* Xlo = xsel ? g_aolo : g_xlo;
    const __nv_bfloat16* Whi = g_whi + (size_t)wsel * 1048576;
    const __nv_bfloat16* Wlo = g_wlo + (size_t)wsel * 1048576;
    float* Y = (ysel_base < 0) ? Yext : sel_buf(ysel_base + z);

    extern __shared__ char smem[];
    const uint32_t sbase = smem_u32(smem);
    const int tid = threadIdx.x;
    const int lane = tid & 31, wid = tid >> 5;
    const int wm = wid & 1, wn = wid >> 1;      // warp tile 64 x 64
    const int m0 = blockIdx.y * 128, n0 = blockIdx.x * 256;

    float acc[4][8][4];
#pragma unroll
    for (int a = 0; a < 4; a++)
#pragma unroll
        for (int b = 0; b < 8; b++)
#pragma unroll
            for (int c = 0; c < 4; c++) acc[a][b][c] = 0.f;

    // chunk loader: 3072 x 16B segments, 12 per thread (always commits)
    auto issue_chunk = [&](int c) {
        if (c < 32) {
            const int k0 = c * 32;
            const uint32_t dstb = sbase + (uint32_t)(c % NSTAGE) * STAGE_B;
#pragma unroll
            for (int it = 0; it < 12; it++) {
                const int id = it * 256 + tid;
                const __nv_bfloat16* src;
                uint32_t dst;
                if (id < 1024) {              // A tiles (hi, lo)
                    const int t = id >> 9;
                    const int r = (id & 511) >> 2, seg = id & 3;
                    src = (t ? Xlo : Xhi) + (size_t)(m0 + r) * 1024 + k0 + seg * 8;
                    dst = dstb + t * A_TILE_B + r * 80 + seg * 16;
                } else {                      // B tiles (hi, lo)
                    const int id2 = id - 1024;
                    const int t = id2 >> 10;
                    const int r = (id2 & 1023) >> 2, seg = id2 & 3;
                    src = (t ? Wlo : Whi) + (size_t)(n0 + r) * 1024 + k0 + seg * 8;
                    dst = dstb + 2 * A_TILE_B + t * B_TILE_B + r * 80 + seg * 16;
                }
                cpasync16(dst, src);
            }
        }
        CP_COMMIT();
    };

    issue_chunk(0);
    issue_chunk(1);
    for (int c = 0; c < 32; c++) {
        CP_WAIT(1);            // chunk c landed (groups retire in order)
        __syncthreads();       // all threads past reads of buf (c-1)%3
        issue_chunk(c + 2);    // writes (c+2)%3 == (c-1)%3; overlaps compute
        const uint32_t st = sbase + (uint32_t)(c % NSTAGE) * STAGE_B;
#pragma unroll
        for (int ks = 0; ks < 2; ks++) {
            const uint32_t arow = (uint32_t)(lane & 15);
            const uint32_t acol = (uint32_t)(ks * 16 + (lane >> 4) * 8) * 2;
            uint32_t ahi[4][4], alo[4][4];
#pragma unroll
            for (int mt = 0; mt < 4; mt++) {
                const uint32_t off = (uint32_t)(wm * 64 + mt * 16 + arow) * 80 + acol;
                ldsm4(ahi[mt], st + off);
                ldsm4(alo[mt], st + A_TILE_B + off);
            }
            const uint32_t brow = (uint32_t)(((lane >> 4) << 3) + (lane & 7));
            const uint32_t bcol = (uint32_t)(ks * 16 + ((lane >> 3) & 1) * 8) * 2;
            uint32_t bhi[4][4], blo[4][4];
#pragma unroll
            for (int nb = 0; nb < 4; nb++) {
                const uint32_t off = (uint32_t)(wn * 64 + nb * 16 + brow) * 80 + bcol;
                ldsm4(bhi[nb], st + 2 * A_TILE_B + off);
                ldsm4(blo[nb], st + 2 * A_TILE_B + B_TILE_B + off);
            }
            // Pass 1: Ahi*Bhi for all (mt,nt) — adjacent MMAs independent.
#pragma unroll
            for (int mt = 0; mt < 4; mt++)
#pragma unroll
                for (int nt = 0; nt < 8; nt++)
                    mma16816(acc[mt][nt], ahi[mt], &bhi[nt >> 1][(nt & 1) * 2]);
            // Pass 2: Ahi*Blo
#pragma unroll
            for (int mt = 0; mt < 4; mt++)
#pragma unroll
                for (int nt = 0; nt < 8; nt++)
                    mma16816(acc[mt][nt], ahi[mt], &blo[nt >> 1][(nt & 1) * 2]);
            // Pass 3: Alo*Bhi  (per-acc order stays hh -> hl -> lh: bitwise same)
#pragma unroll
            for (int mt = 0; mt < 4; mt++)
#pragma unroll
                for (int nt = 0; nt < 8; nt++)
                    mma16816(acc[mt][nt], alo[mt], &bhi[nt >> 1][(nt & 1) * 2]);
        }
    }

    const int mrow = lane >> 2, ncol = (lane & 3) * 2;
#pragma unroll
    for (int mt = 0; mt < 4; mt++)
#pragma unroll
        for (int nt = 0; nt < 8; nt++) {
            const int m = m0 + wm * 64 + mt * 16 + mrow;
            const int n = n0 + wn * 64 + nt * 8 + ncol;
            const float b0 = __ldg(&bias[n]), b1 = __ldg(&bias[n + 1]);
            float* y0 = Y + (size_t)m * 1024 + n;
            float* y1 = Y + (size_t)(m + 8) * 1024 + n;
            *(float2*)y0 = make_float2(acc[mt][nt][0] + b0, acc[mt][nt][1] + b1);
            *(float2*)y1 = make_float2(acc[mt][nt][2] + b0, acc[mt][nt][3] + b1);
        }
}

// ---------------------------------------------------------------------------
// feat_kv v3: 512 threads (16 warps), grid 1024 = 64 bh x 16 chunks (256 rows),
// tiles of 64 rows.  Thread owns 4e x 4d -> 2 CTAs/SM, 50% occupancy.
// ---------------------------------------------------------------------------
#define FK_SMEM 82944
__global__ __launch_bounds__(512, 2) void feat_kv_kernel(const float* __restrict__ Pm)
{
    extern __shared__ float sm[];
    float (*Ps)[68]  = (float(*)[68])sm;
    float (*ks)[64]  = (float(*)[64])(sm + 4352);
    float (*vs)[64]  = (float(*)[64])(sm + 8448);
    float (*kf)[128] = (float(*)[128])(sm + 12544);

    const int tid = threadIdx.x, lane = tid & 31, warp = tid >> 5;
    const int bid = blockIdx.x;
    const int bh = bid >> 4, ch = bid & 15;
    const int b = bh >> 4, h = bh & 15;
    const size_t hb = (size_t)(b * N_) * E_ + h * 64;
    const int row0 = ch * 256;

    for (int i = tid; i < 4096; i += 512) Ps[i >> 6][i & 63] = Pm[i];
    __syncthreads();

    const int eg = tid >> 4, dg = tid & 15;
    float acc[4][4];
#pragma unroll
    for (int i = 0; i < 4; i++)
#pragma unroll
        for (int j = 0; j < 4; j++) acc[i][j] = 0.f;

    for (int t0 = 0; t0 < 256; t0 += 64) {
#pragma unroll
        for (int j = 0; j < 4; j++) {
            const int rl = warp * 4 + j;
            const int row = row0 + t0 + rl;
            const float* kr = g_k + hb + (size_t)row * E_;
            const float* vr = g_v + hb + (size_t)row * E_;
            float2 k2 = ((const float2*)kr)[lane];
            float2 v2 = ((const float2*)vr)[lane];
            ((float2*)vs[rl])[lane] = v2;
            float ss = k2.x * k2.x + k2.y * k2.y;
#pragma unroll
            for (int off = 16; off; off >>= 1) ss += __shfl_xor_sync(0xffffffffu, ss, off);
            float inv = 1.0f / (sqrtf(ss) + EPSN);
            ((float2*)ks[rl])[lane] = make_float2(k2.x * inv, k2.y * inv);
        }
        float p0[4], p1[4];
#pragma unroll
        for (int j = 0; j < 4; j++) { p0[j] = 0.f; p1[j] = 0.f; }
#pragma unroll
        for (int d4 = 0; d4 < 16; d4++) {
            float4 pa = *(const float4*)&Ps[lane][d4 * 4];
            float4 pb = *(const float4*)&Ps[lane + 32][d4 * 4];
#pragma unroll
            for (int j = 0; j < 4; j++) {
                float4 kk = *(const float4*)&ks[warp * 4 + j][d4 * 4];
                p0[j] += kk.x*pa.x + kk.y*pa.y + kk.z*pa.z + kk.w*pa.w;
                p1[j] += kk.x*pb.x + kk.y*pb.y + kk.z*pb.z + kk.w*pb.w;
            }
        }
#pragma unroll
        for (int j = 0; j < 4; j++) {
            const int rl = warp * 4 + j;
            float s0, c0, s1, c1;
            __sincosf(p0[j] * SCALE, &s0, &c0);
            __sincosf(p1[j] * SCALE, &s1, &c1);
            kf[rl][lane]      = s0 * FSCALE;
            kf[rl][lane + 32] = s1 * FSCALE;
            kf[rl][64 + lane] = c0 * FSCALE;
            kf[rl][96 + lane] = c1 * FSCALE;
        }
        __syncthreads();
#pragma unroll 8
        for (int r = 0; r < 64; r++) {
            float4 v4 = *(const float4*)&vs[r][dg * 4];
            float4 f4 = *(const float4*)&kf[r][eg * 4];
            float fa[4] = {f4.x, f4.y, f4.z, f4.w};
#pragma unroll
            for (int i = 0; i < 4; i++) {
                acc[i][0] = fmaf(fa[i], v4.x, acc[i][0]);
                acc[i][1] = fmaf(fa[i], v4.y, acc[i][1]);
                acc[i][2] = fmaf(fa[i], v4.z, acc[i][2]);
                acc[i][3] = fmaf(fa[i], v4.w, acc[i][3]);
            }
        }
        __syncthreads();
    }

    float* outp = g_kvp + (size_t)bid * 8192;
#pragma unroll
    for (int i = 0; i < 4; i++)
        *(float4*)(outp + (eg * 4 + i) * 64 + dg * 4) =
            make_float4(acc[i][0], acc[i][1], acc[i][2], acc[i][3]);
}

// ---------------------------------------------------------------------------
__global__ __launch_bounds__(256) void kv_reduce_kernel()
{
    int bh = blockIdx.x, tid = threadIdx.x;
    const float4* src = (const float4*)(g_kvp + (size_t)bh * 16 * 8192);
    float4* dst = (float4*)(g_kv + (size_t)bh * 8192);
    for (int i = tid; i < 2048; i += 256) {
        float4 s = src[i];
#pragma unroll
        for (int c = 1; c < 16; c++) {
            float4 t = src[c * 2048 + i];
            s.x += t.x; s.y += t.y; s.z += t.z; s.w += t.w;
        }
        dst[i] = s;
    }
}

// ---------------------------------------------------------------------------
// o_feat v3: 512 threads (16 warps), grid 1024; writes ao bf16 hi/lo splits.
// ---------------------------------------------------------------------------
#define OF_SMEM 100352
__global__ __launch_bounds__(512, 2) void o_feat_kernel(const float* __restrict__ Pm)
{
    extern __shared__ float sm[];
    float (*Ps)[68]   = (float(*)[68])sm;
    float (*kvt)[132] = (float(*)[132])(sm + 4352);
    float (*qs)[64]   = (float(*)[64])(sm + 12800);
    float (*qf)[128]  = (float(*)[128])(sm + 16896);

    const int tid = threadIdx.x, lane = tid & 31, warp = tid >> 5;
    const int bid = blockIdx.x;
    const int bh = bid >> 4, ch = bid & 15;
    const int b = bh >> 4, h = bh & 15;
    const size_t hb = (size_t)(b * N_) * E_ + h * 64;
    const int row0 = ch * 256;

    for (int i = tid; i < 4096; i += 512) Ps[i >> 6][i & 63] = Pm[i];
    {
        const float* kvg = g_kv + (size_t)bh * 8192;
        for (int i = tid; i < 8192; i += 512) kvt[i & 63][i >> 6] = kvg[i];
    }
    __syncthreads();

    for (int t0 = 0; t0 < 256; t0 += 64) {
#pragma unroll
        for (int j = 0; j < 4; j++) {
            const int rl = warp * 4 + j;
            const int row = row0 + t0 + rl;
            const float* qr = g_q + hb + (size_t)row * E_;
            float2 q2 = ((const float2*)qr)[lane];
            float ss = q2.x * q2.x + q2.y * q2.y;
#pragma unroll
            for (int off = 16; off; off >>= 1) ss += __shfl_xor_sync(0xffffffffu, ss, off);
            float inv = 1.0f / (sqrtf(ss) + EPSN);
            ((float2*)qs[rl])[lane] = make_float2(q2.x * inv, q2.y * inv);
        }
        float p0[4], p1[4];
#pragma unroll
        for (int j = 0; j < 4; j++) { p0[j] = 0.f; p1[j] = 0.f; }
#pragma unroll
        for (int d4 = 0; d4 < 16; d4++) {
            float4 pa = *(const float4*)&Ps[lane][d4 * 4];
            float4 pb = *(const float4*)&Ps[lane + 32][d4 * 4];
#pragma unroll
            for (int j = 0; j < 4; j++) {
                float4 kk = *(const float4*)&qs[warp * 4 + j][d4 * 4];
                p0[j] += kk.x*pa.x + kk.y*pa.y + kk.z*pa.z + kk.w*pa.w;
                p1[j] += kk.x*pb.x + kk.y*pb.y + kk.z*pb.z + kk.w*pb.w;
            }
        }
#pragma unroll
        for (int j = 0; j < 4; j++) {
            const int rl = warp * 4 + j;
            float s0, c0, s1, c1;
            __sincosf(p0[j] * SCALE, &s0, &c0);
            __sincosf(p1[j] * SCALE, &s1, &c1);
            qf[rl][lane]      = s0 * FSCALE;
            qf[rl][lane + 32] = s1 * FSCALE;
            qf[rl][64 + lane] = c0 * FSCALE;
            qf[rl][96 + lane] = c1 * FSCALE;
        }
        __syncthreads();
        float o0[4], o1[4];
#pragma unroll
        for (int j = 0; j < 4; j++) { o0[j] = 0.f; o1[j] = 0.f; }
#pragma unroll
        for (int e4 = 0; e4 < 32; e4++) {
            float4 kv0 = *(const float4*)&kvt[lane][e4 * 4];
            float4 kv1 = *(const float4*)&kvt[lane + 32][e4 * 4];
#pragma unroll
            for (int j = 0; j < 4; j++) {
                float4 q4 = *(const float4*)&qf[warp * 4 + j][e4 * 4];
                o0[j] += q4.x*kv0.x + q4.y*kv0.y + q4.z*kv0.z + q4.w*kv0.w;
                o1[j] += q4.x*kv1.x + q4.y*kv1.y + q4.z*kv1.z + q4.w*kv1.w;
            }
        }
#pragma unroll
        for (int j = 0; j < 4; j++) {
            const int row = row0 + t0 + warp * 4 + j;
            const size_t idx = hb + (size_t)row * E_ + lane;
            __nv_bfloat16 h0 = __float2bfloat16(o0[j]);
            __nv_bfloat16 h1 = __float2bfloat16(o1[j]);
            g_aohi[idx]      = h0;
            g_aohi[idx + 32] = h1;
            g_aolo[idx]      = __float2bfloat16(o0[j] - __bfloat162float(h0));
            g_aolo[idx + 32] = __float2bfloat16(o1[j] - __bfloat162float(h1));
        }
        __syncthreads();
    }
}

// ---------------------------------------------------------------------------
extern "C" void kernel_launch(void* const* d_in, const int* in_sizes, int n_in,
                              void* d_out, int out_size)
{
    const float* x  = (const float*)d_in[0];
    const float* Wq = (const float*)d_in[1];
    const float* bq = (const float*)d_in[2];
    const float* Wk = (const float*)d_in[3];
    const float* bk = (const float*)d_in[4];
    const float* Wv = (const float*)d_in[5];
    const float* bv = (const float*)d_in[6];
    const float* Wo = (const float*)d_in[7];
    const float* bo = (const float*)d_in[8];
    const float* P  = (const float*)d_in[9];
    float* out = (float*)d_out;

    cudaFuncSetAttribute(gemm_mma,
                         cudaFuncAttributeMaxDynamicSharedMemorySize, NSTAGE * STAGE_B);
    cudaFuncSetAttribute(feat_kv_kernel,
                         cudaFuncAttributeMaxDynamicSharedMemorySize, FK_SMEM);
    cudaFuncSetAttribute(o_feat_kernel,
                         cudaFuncAttributeMaxDynamicSharedMemorySize, OF_SMEM);

    conv_x<<<16384, 256>>>(x);
    conv_w<<<dim3(1024, 4), 256>>>(Wq, Wk, Wv, Wo);

    // fused q/k/v projections
    gemm_mma<<<dim3(4, 128, 3), 256, NSTAGE * STAGE_B>>>(
        0, 0, bq, bk, bv, nullptr, 0);

    feat_kv_kernel<<<1024, 512, FK_SMEM>>>(P);
    kv_reduce_kernel<<<64, 256>>>();
    o_feat_kernel<<<1024, 512, OF_SMEM>>>(P);     // -> g_aohi/g_aolo

    // output projection
    gemm_mma<<<dim3(4, 128, 1), 256, NSTAGE * STAGE_B>>>(
        1, 3, bo, bo, bo, out, -1);
}

// round 16
// speedup vs baseline: 1.0253x; 1.0253x over previous
#include <cuda_runtime.h>
#include <cuda_bf16.h>
#include <math.h>
#include <cstdint>

// Problem constants
#define B_    4
#define N_    4096
#define E_    1024
#define H_    16
#define MTOT  16384        // B*N
#define EPSN  1e-4f
#define SCALE 2.0f         // H^0.25
#define FSCALE 0.125f      // PD^-0.5

// ---------------------------------------------------------------------------
// Scratch (device globals: allocation-free rule)
// ---------------------------------------------------------------------------
__device__ float g_q [16777216];     // (B,N,E) q proj fp32
__device__ float g_k [16777216];     // (B,N,E) k proj fp32
__device__ float g_v [16777216];     // (B,N,E) v proj fp32
__device__ float g_kvp[8388608];     // per block partial kv (128x64), 1024 blocks
__device__ float g_kv [524288];      // per bh kv (128x64)
__device__ __nv_bfloat16 g_xhi [16777216];
__device__ __nv_bfloat16 g_xlo [16777216];
__device__ __nv_bfloat16 g_aohi[16777216];
__device__ __nv_bfloat16 g_aolo[16777216];
__device__ __nv_bfloat16 g_whi [4194304];   // 4 x 1024x1024
__device__ __nv_bfloat16 g_wlo [4194304];

__device__ __forceinline__ float* sel_buf(int s) {
    return s == 0 ? g_q : (s == 1 ? g_k : g_v);
}

// ---------------------------------------------------------------------------
// PTX helpers (base-target sm_103 safe: mma.sync / ldmatrix / cp.async only)
// ---------------------------------------------------------------------------
__device__ __forceinline__ uint32_t smem_u32(const void* p) {
    uint32_t a;
    asm("{ .reg .u64 t; cvta.to.shared.u64 t, %1; cvt.u32.u64 %0, t; }"
        : "=r"(a) : "l"(p));
    return a;
}
__device__ __forceinline__ void cpasync16(uint32_t dst, const void* src) {
    asm volatile("cp.async.cg.shared.global [%0], [%1], 16;" :: "r"(dst), "l"(src));
}
#define CP_COMMIT()  asm volatile("cp.async.commit_group;" ::: "memory")
#define CP_WAIT(n)   asm volatile("cp.async.wait_group %0;" :: "n"(n) : "memory")

__device__ __forceinline__ void ldsm4(uint32_t* r, uint32_t addr) {
    asm volatile("ldmatrix.sync.aligned.m8n8.x4.shared.b16 {%0,%1,%2,%3}, [%4];"
                 : "=r"(r[0]), "=r"(r[1]), "=r"(r[2]), "=r"(r[3]) : "r"(addr));
}
__device__ __forceinline__ void mma16816(float* d, const uint32_t* a, const uint32_t* b) {
    asm volatile(
        "mma.sync.aligned.m16n8k16.row.col.f32.bf16.bf16.f32 "
        "{%0,%1,%2,%3}, {%4,%5,%6,%7}, {%8,%9}, {%0,%1,%2,%3};"
        : "+f"(d[0]), "+f"(d[1]), "+f"(d[2]), "+f"(d[3])
        : "r"(a[0]), "r"(a[1]), "r"(a[2]), "r"(a[3]), "r"(b[0]), "r"(b[1]));
}

// ---------------------------------------------------------------------------
// Split conversions: fp32 -> bf16 hi + bf16 lo.
// ---------------------------------------------------------------------------
__device__ __forceinline__ void split_store(const float4 v, __nv_bfloat16* hi,
                                            __nv_bfloat16* lo, int i)
{
    __nv_bfloat16 h0 = __float2bfloat16(v.x);
    __nv_bfloat16 h1 = __float2bfloat16(v.y);
    __nv_bfloat16 h2 = __float2bfloat16(v.z);
    __nv_bfloat16 h3 = __float2bfloat16(v.w);
    __nv_bfloat162* hp = (__nv_bfloat162*)hi;
    __nv_bfloat162* lp = (__nv_bfloat162*)lo;
    hp[i * 2]     = __nv_bfloat162(h0, h1);
    hp[i * 2 + 1] = __nv_bfloat162(h2, h3);
    lp[i * 2]     = __nv_bfloat162(__float2bfloat16(v.x - __bfloat162float(h0)),
                                   __float2bfloat16(v.y - __bfloat162float(h1)));
    lp[i * 2 + 1] = __nv_bfloat162(__float2bfloat16(v.z - __bfloat162float(h2)),
                                   __float2bfloat16(v.w - __bfloat162float(h3)));
}

__global__ __launch_bounds__(256) void conv_x(const float* __restrict__ src)
{
    int i = blockIdx.x * 256 + threadIdx.x;
    split_store(((const float4*)src)[i], g_xhi, g_xlo, i);
}

__global__ __launch_bounds__(256) void conv_w(
    const float* __restrict__ w0, const float* __restrict__ w1,
    const float* __restrict__ w2, const float* __restrict__ w3)
{
    int z = blockIdx.y;
    const float* src = z == 0 ? w0 : (z == 1 ? w1 : (z == 2 ? w2 : w3));
    int i = blockIdx.x * 256 + threadIdx.x;
    split_store(((const float4*)src)[i],
                g_whi + (size_t)z * 1048576, g_wlo + (size_t)z * 1048576, i);
}

// ---------------------------------------------------------------------------
// Tensor-core GEMM (NT) via mma.sync bf16 split:
// Y[16384,1024] = X @ W^T + bias.  grid (4, 128, nz); z selects W/bias/dst.
// 128x256 block, K-chunk 32, *512* threads (16 warps = 4/SMSP, warp tile
// 64x32), 3-stage cp.async pipeline.  More warps/SMSP to hide HMMA+ldsm
// latency (previous rounds all ran 2/SMSP).
// ---------------------------------------------------------------------------
#define A_TILE_B 10240     // 128 rows * 80 bytes
#define B_TILE_B 20480     // 256 rows * 80 bytes
#define STAGE_B  61440     // Ahi|Alo|Bhi|Blo
#define NSTAGE   3
__global__ __launch_bounds__(512, 1) void gemm_mma(
    int xsel, int wsel_base,
    const float* __restrict__ bias0, const float* __restrict__ bias1,
    const float* __restrict__ bias2,
    float* __restrict__ Yext, int ysel_base)
{
    const int z = blockIdx.z;
    const int wsel = wsel_base + z;
    const float* bias = z == 0 ? bias0 : (z == 1 ? bias1 : bias2);
    const __nv_bfloat16* Xhi = xsel ? g_aohi : g_xhi;
    const __nv_bfloat16* Xlo = xsel ? g_aolo : g_xlo;
    const __nv_bfloat16* Whi = g_whi + (size_t)wsel * 1048576;
    const __nv_bfloat16* Wlo = g_wlo + (size_t)wsel * 1048576;
    float* Y = (ysel_base < 0) ? Yext : sel_buf(ysel_base + z);

    extern __shared__ char smem[];
    const uint32_t sbase = smem_u32(smem);
    const int tid = threadIdx.x;
    const int lane = tid & 31, wid = tid >> 5;   // 16 warps
    const int wm = wid & 1, wn = wid >> 1;        // 2 x 8 warp grid, 64x32 tile
    const int m0 = blockIdx.y * 128, n0 = blockIdx.x * 256;

    float acc[4][4][4];
#pragma unroll
    for (int a = 0; a < 4; a++)
#pragma unroll
        for (int b = 0; b < 4; b++)
#pragma unroll
            for (int c = 0; c < 4; c++) acc[a][b][c] = 0.f;

    // chunk loader: 3072 x 16B segments, 6 per thread (region uniform per it)
    auto issue_chunk = [&](int c) {
        if (c < 32) {
            const int k0 = c * 32;
            const uint32_t dstb = sbase + (uint32_t)(c % NSTAGE) * STAGE_B;
#pragma unroll
            for (int it = 0; it < 6; it++) {
                const int id = it * 512 + tid;
                const __nv_bfloat16* src;
                uint32_t dst;
                if (id < 1024) {              // A tiles (hi, lo)
                    const int t = id >> 9;
                    const int r = (id & 511) >> 2, seg = id & 3;
                    src = (t ? Xlo : Xhi) + (size_t)(m0 + r) * 1024 + k0 + seg * 8;
                    dst = dstb + t * A_TILE_B + r * 80 + seg * 16;
                } else {                      // B tiles (hi, lo)
                    const int id2 = id - 1024;
                    const int t = id2 >> 10;
                    const int r = (id2 & 1023) >> 2, seg = id2 & 3;
                    src = (t ? Wlo : Whi) + (size_t)(n0 + r) * 1024 + k0 + seg * 8;
                    dst = dstb + 2 * A_TILE_B + t * B_TILE_B + r * 80 + seg * 16;
                }
                cpasync16(dst, src);
            }
        }
        CP_COMMIT();
    };

    issue_chunk(0);
    issue_chunk(1);
    for (int c = 0; c < 32; c++) {
        CP_WAIT(1);            // chunk c landed (groups retire in order)
        __syncthreads();       // all threads past reads of buf (c-1)%3
        issue_chunk(c + 2);    // writes (c+2)%3 == (c-1)%3; overlaps compute
        const uint32_t st = sbase + (uint32_t)(c % NSTAGE) * STAGE_B;
#pragma unroll
        for (int ks = 0; ks < 2; ks++) {
            const uint32_t arow = (uint32_t)(lane & 15);
            const uint32_t acol = (uint32_t)(ks * 16 + (lane >> 4) * 8) * 2;
            uint32_t ahi[4][4], alo[4][4];
#pragma unroll
            for (int mt = 0; mt < 4; mt++) {
                const uint32_t off = (uint32_t)(wm * 64 + mt * 16 + arow) * 80 + acol;
                ldsm4(ahi[mt], st + off);
                ldsm4(alo[mt], st + A_TILE_B + off);
            }
            const uint32_t brow = (uint32_t)(((lane >> 4) << 3) + (lane & 7));
            const uint32_t bcol = (uint32_t)(ks * 16 + ((lane >> 3) & 1) * 8) * 2;
            uint32_t bhi[2][4], blo[2][4];
#pragma unroll
            for (int nb = 0; nb < 2; nb++) {
                const uint32_t off = (uint32_t)(wn * 32 + nb * 16 + brow) * 80 + bcol;
                ldsm4(bhi[nb], st + 2 * A_TILE_B + off);
                ldsm4(blo[nb], st + 2 * A_TILE_B + B_TILE_B + off);
            }
            // per-accumulator contribution order stays hh -> hl -> lh
#pragma unroll
            for (int mt = 0; mt < 4; mt++)
#pragma unroll
                for (int nt = 0; nt < 4; nt++)
                    mma16816(acc[mt][nt], ahi[mt], &bhi[nt >> 1][(nt & 1) * 2]);
#pragma unroll
            for (int mt = 0; mt < 4; mt++)
#pragma unroll
                for (int nt = 0; nt < 4; nt++)
                    mma16816(acc[mt][nt], ahi[mt], &blo[nt >> 1][(nt & 1) * 2]);
#pragma unroll
            for (int mt = 0; mt < 4; mt++)
#pragma unroll
                for (int nt = 0; nt < 4; nt++)
                    mma16816(acc[mt][nt], alo[mt], &bhi[nt >> 1][(nt & 1) * 2]);
        }
    }

    const int mrow = lane >> 2, ncol = (lane & 3) * 2;
#pragma unroll
    for (int mt = 0; mt < 4; mt++)
#pragma unroll
        for (int nt = 0; nt < 4; nt++) {
            const int m = m0 + wm * 64 + mt * 16 + mrow;
            const int n = n0 + wn * 32 + nt * 8 + ncol;
            const float b0 = __ldg(&bias[n]), b1 = __ldg(&bias[n + 1]);
            float* y0 = Y + (size_t)m * 1024 + n;
            float* y1 = Y + (size_t)(m + 8) * 1024 + n;
            *(float2*)y0 = make_float2(acc[mt][nt][0] + b0, acc[mt][nt][1] + b1);
            *(float2*)y1 = make_float2(acc[mt][nt][2] + b0, acc[mt][nt][3] + b1);
        }
}

// ---------------------------------------------------------------------------
// feat_kv v3: 512 threads (16 warps), grid 1024 = 64 bh x 16 chunks (256 rows),
// tiles of 64 rows.  Thread owns 4e x 4d -> 2 CTAs/SM, 50% occupancy.
// ---------------------------------------------------------------------------
#define FK_SMEM 82944
__global__ __launch_bounds__(512, 2) void feat_kv_kernel(const float* __restrict__ Pm)
{
    extern __shared__ float sm[];
    float (*Ps)[68]  = (float(*)[68])sm;
    float (*ks)[64]  = (float(*)[64])(sm + 4352);
    float (*vs)[64]  = (float(*)[64])(sm + 8448);
    float (*kf)[128] = (float(*)[128])(sm + 12544);

    const int tid = threadIdx.x, lane = tid & 31, warp = tid >> 5;
    const int bid = blockIdx.x;
    const int bh = bid >> 4, ch = bid & 15;
    const int b = bh >> 4, h = bh & 15;
    const size_t hb = (size_t)(b * N_) * E_ + h * 64;
    const int row0 = ch * 256;

    for (int i = tid; i < 4096; i += 512) Ps[i >> 6][i & 63] = Pm[i];
    __syncthreads();

    const int eg = tid >> 4, dg = tid & 15;
    float acc[4][4];
#pragma unroll
    for (int i = 0; i < 4; i++)
#pragma unroll
        for (int j = 0; j < 4; j++) acc[i][j] = 0.f;

    for (int t0 = 0; t0 < 256; t0 += 64) {
#pragma unroll
        for (int j = 0; j < 4; j++) {
            const int rl = warp * 4 + j;
            const int row = row0 + t0 + rl;
            const float* kr = g_k + hb + (size_t)row * E_;
            const float* vr = g_v + hb + (size_t)row * E_;
            float2 k2 = ((const float2*)kr)[lane];
            float2 v2 = ((const float2*)vr)[lane];
            ((float2*)vs[rl])[lane] = v2;
            float ss = k2.x * k2.x + k2.y * k2.y;
#pragma unroll
            for (int off = 16; off; off >>= 1) ss += __shfl_xor_sync(0xffffffffu, ss, off);
            float inv = 1.0f / (sqrtf(ss) + EPSN);
            ((float2*)ks[rl])[lane] = make_float2(k2.x * inv, k2.y * inv);
        }
        float p0[4], p1[4];
#pragma unroll
        for (int j = 0; j < 4; j++) { p0[j] = 0.f; p1[j] = 0.f; }
#pragma unroll
        for (int d4 = 0; d4 < 16; d4++) {
            float4 pa = *(const float4*)&Ps[lane][d4 * 4];
            float4 pb = *(const float4*)&Ps[lane + 32][d4 * 4];
#pragma unroll
            for (int j = 0; j < 4; j++) {
                float4 kk = *(const float4*)&ks[warp * 4 + j][d4 * 4];
                p0[j] += kk.x*pa.x + kk.y*pa.y + kk.z*pa.z + kk.w*pa.w;
                p1[j] += kk.x*pb.x + kk.y*pb.y + kk.z*pb.z + kk.w*pb.w;
            }
        }
#pragma unroll
        for (int j = 0; j < 4; j++) {
            const int rl = warp * 4 + j;
            float s0, c0, s1, c1;
            __sincosf(p0[j] * SCALE, &s0, &c0);
            __sincosf(p1[j] * SCALE, &s1, &c1);
            kf[rl][lane]      = s0 * FSCALE;
            kf[rl][lane + 32] = s1 * FSCALE;
            kf[rl][64 + lane] = c0 * FSCALE;
            kf[rl][96 + lane] = c1 * FSCALE;
        }
        __syncthreads();
#pragma unroll 8
        for (int r = 0; r < 64; r++) {
            float4 v4 = *(const float4*)&vs[r][dg * 4];
            float4 f4 = *(const float4*)&kf[r][eg * 4];
            float fa[4] = {f4.x, f4.y, f4.z, f4.w};
#pragma unroll
            for (int i = 0; i < 4; i++) {
                acc[i][0] = fmaf(fa[i], v4.x, acc[i][0]);
                acc[i][1] = fmaf(fa[i], v4.y, acc[i][1]);
                acc[i][2] = fmaf(fa[i], v4.z, acc[i][2]);
                acc[i][3] = fmaf(fa[i], v4.w, acc[i][3]);
            }
        }
        __syncthreads();
    }

    float* outp = g_kvp + (size_t)bid * 8192;
#pragma unroll
    for (int i = 0; i < 4; i++)
        *(float4*)(outp + (eg * 4 + i) * 64 + dg * 4) =
            make_float4(acc[i][0], acc[i][1], acc[i][2], acc[i][3]);
}

// ---------------------------------------------------------------------------
__global__ __launch_bounds__(256) void kv_reduce_kernel()
{
    int bh = blockIdx.x, tid = threadIdx.x;
    const float4* src = (const float4*)(g_kvp + (size_t)bh * 16 * 8192);
    float4* dst = (float4*)(g_kv + (size_t)bh * 8192);
    for (int i = tid; i < 2048; i += 256) {
        float4 s = src[i];
#pragma unroll
        for (int c = 1; c < 16; c++) {
            float4 t = src[c * 2048 + i];
            s.x += t.x; s.y += t.y; s.z += t.z; s.w += t.w;
        }
        dst[i] = s;
    }
}

// ---------------------------------------------------------------------------
// o_feat v3: 512 threads (16 warps), grid 1024; writes ao bf16 hi/lo splits.
// ---------------------------------------------------------------------------
#define OF_SMEM 100352
__global__ __launch_bounds__(512, 2) void o_feat_kernel(const float* __restrict__ Pm)
{
    extern __shared__ float sm[];
    float (*Ps)[68]   = (float(*)[68])sm;
    float (*kvt)[132] = (float(*)[132])(sm + 4352);
    float (*qs)[64]   = (float(*)[64])(sm + 12800);
    float (*qf)[128]  = (float(*)[128])(sm + 16896);

    const int tid = threadIdx.x, lane = tid & 31, warp = tid >> 5;
    const int bid = blockIdx.x;
    const int bh = bid >> 4, ch = bid & 15;
    const int b = bh >> 4, h = bh & 15;
    const size_t hb = (size_t)(b * N_) * E_ + h * 64;
    const int row0 = ch * 256;

    for (int i = tid; i < 4096; i += 512) Ps[i >> 6][i & 63] = Pm[i];
    {
        const float* kvg = g_kv + (size_t)bh * 8192;
        for (int i = tid; i < 8192; i += 512) kvt[i & 63][i >> 6] = kvg[i];
    }
    __syncthreads();

    for (int t0 = 0; t0 < 256; t0 += 64) {
#pragma unroll
        for (int j = 0; j < 4; j++) {
            const int rl = warp * 4 + j;
            const int row = row0 + t0 + rl;
            const float* qr = g_q + hb + (size_t)row * E_;
            float2 q2 = ((const float2*)qr)[lane];
            float ss = q2.x * q2.x + q2.y * q2.y;
#pragma unroll
            for (int off = 16; off; off >>= 1) ss += __shfl_xor_sync(0xffffffffu, ss, off);
            float inv = 1.0f / (sqrtf(ss) + EPSN);
            ((float2*)qs[rl])[lane] = make_float2(q2.x * inv, q2.y * inv);
        }
        float p0[4], p1[4];
#pragma unroll
        for (int j = 0; j < 4; j++) { p0[j] = 0.f; p1[j] = 0.f; }
#pragma unroll
        for (int d4 = 0; d4 < 16; d4++) {
            float4 pa = *(const float4*)&Ps[lane][d4 * 4];
            float4 pb = *(const float4*)&Ps[lane + 32][d4 * 4];
#pragma unroll
            for (int j = 0; j < 4; j++) {
                float4 kk = *(const float4*)&qs[warp * 4 + j][d4 * 4];
                p0[j] += kk.x*pa.x + kk.y*pa.y + kk.z*pa.z + kk.w*pa.w;
                p1[j] += kk.x*pb.x + kk.y*pb.y + kk.z*pb.z + kk.w*pb.w;
            }
        }
#pragma unroll
        for (int j = 0; j < 4; j++) {
            const int rl = warp * 4 + j;
            float s0, c0, s1, c1;
            __sincosf(p0[j] * SCALE, &s0, &c0);
            __sincosf(p1[j] * SCALE, &s1, &c1);
            qf[rl][lane]      = s0 * FSCALE;
            qf[rl][lane + 32] = s1 * FSCALE;
            qf[rl][64 + lane] = c0 * FSCALE;
            qf[rl][96 + lane] = c1 * FSCALE;
        }
        __syncthreads();
        float o0[4], o1[4];
#pragma unroll
        for (int j = 0; j < 4; j++) { o0[j] = 0.f; o1[j] = 0.f; }
#pragma unroll
        for (int e4 = 0; e4 < 32; e4++) {
            float4 kv0 = *(const float4*)&kvt[lane][e4 * 4];
            float4 kv1 = *(const float4*)&kvt[lane + 32][e4 * 4];
#pragma unroll
            for (int j = 0; j < 4; j++) {
                float4 q4 = *(const float4*)&qf[warp * 4 + j][e4 * 4];
                o0[j] += q4.x*kv0.x + q4.y*kv0.y + q4.z*kv0.z + q4.w*kv0.w;
                o1[j] += q4.x*kv1.x + q4.y*kv1.y + q4.z*kv1.z + q4.w*kv1.w;
            }
        }
#pragma unroll
        for (int j = 0; j < 4; j++) {
            const int row = row0 + t0 + warp * 4 + j;
            const size_t idx = hb + (size_t)row * E_ + lane;
            __nv_bfloat16 h0 = __float2bfloat16(o0[j]);
            __nv_bfloat16 h1 = __float2bfloat16(o1[j]);
            g_aohi[idx]      = h0;
            g_aohi[idx + 32] = h1;
            g_aolo[idx]      = __float2bfloat16(o0[j] - __bfloat162float(h0));
            g_aolo[idx + 32] = __float2bfloat16(o1[j] - __bfloat162float(h1));
        }
        __syncthreads();
    }
}

// ---------------------------------------------------------------------------
extern "C" void kernel_launch(void* const* d_in, const int* in_sizes, int n_in,
                              void* d_out, int out_size)
{
    const float* x  = (const float*)d_in[0];
    const float* Wq = (const float*)d_in[1];
    const float* bq = (const float*)d_in[2];
    const float* Wk = (const float*)d_in[3];
    const float* bk = (const float*)d_in[4];
    const float* Wv = (const float*)d_in[5];
    const float* bv = (const float*)d_in[6];
    const float* Wo = (const float*)d_in[7];
    const float* bo = (const float*)d_in[8];
    const float* P  = (const float*)d_in[9];
    float* out = (float*)d_out;

    cudaFuncSetAttribute(gemm_mma,
                         cudaFuncAttributeMaxDynamicSharedMemorySize, NSTAGE * STAGE_B);
    cudaFuncSetAttribute(feat_kv_kernel,
                         cudaFuncAttributeMaxDynamicSharedMemorySize, FK_SMEM);
    cudaFuncSetAttribute(o_feat_kernel,
                         cudaFuncAttributeMaxDynamicSharedMemorySize, OF_SMEM);

    conv_x<<<16384, 256>>>(x);
    conv_w<<<dim3(1024, 4), 256>>>(Wq, Wk, Wv, Wo);

    // fused q/k/v projections (512-thread GEMM: 4 warps/SMSP)
    gemm_mma<<<dim3(4, 128, 3), 512, NSTAGE * STAGE_B>>>(
        0, 0, bq, bk, bv, nullptr, 0);

    feat_kv_kernel<<<1024, 512, FK_SMEM>>>(P);
    kv_reduce_kernel<<<64, 256>>>();
    o_feat_kernel<<<1024, 512, OF_SMEM>>>(P);     // -> g_aohi/g_aolo

    // output projection
    gemm_mma<<<dim3(4, 128, 1), 512, NSTAGE * STAGE_B>>>(
        1, 3, bo, bo, bo, out, -1);
}

// round 17
// speedup vs baseline: 1.2756x; 1.2441x over previous
#include <cuda_runtime.h>
#include <cuda_fp16.h>
#include <math.h>
#include <cstdint>

// Problem constants
#define B_    4
#define N_    4096
#define E_    1024
#define H_    16
#define MTOT  16384        // B*N
#define EPSN  1e-4f
#define SCALE 2.0f         // H^0.25
#define FSCALE 0.125f      // PD^-0.5

// ---------------------------------------------------------------------------
// Scratch (device globals: allocation-free rule)
// ---------------------------------------------------------------------------
__device__ float g_q [16777216];     // (B,N,E) q proj fp32
__device__ float g_k [16777216];     // (B,N,E) k proj fp32
__device__ float g_v [16777216];     // (B,N,E) v proj fp32
__device__ float g_kvp[8388608];     // per block partial kv (128x64), 1024 blocks
__device__ float g_kv [524288];      // per bh kv (128x64)
__device__ __half g_xhi [16777216];  // X (or ao) fp16 hi
__device__ __half g_xlo [16777216];  // X (or ao) fp16 lo
__device__ __half g_aohi[16777216];
__device__ __half g_aolo[16777216];
__device__ __half g_wh  [4194304];   // 4 x 1024x1024 W single fp16

__device__ __forceinline__ float* sel_buf(int s) {
    return s == 0 ? g_q : (s == 1 ? g_k : g_v);
}

// ---------------------------------------------------------------------------
// PTX helpers (base-target sm_103 safe: mma.sync / ldmatrix / cp.async only)
// ---------------------------------------------------------------------------
__device__ __forceinline__ uint32_t smem_u32(const void* p) {
    uint32_t a;
    asm("{ .reg .u64 t; cvta.to.shared.u64 t, %1; cvt.u32.u64 %0, t; }"
        : "=r"(a) : "l"(p));
    return a;
}
__device__ __forceinline__ void cpasync16(uint32_t dst, const void* src) {
    asm volatile("cp.async.cg.shared.global [%0], [%1], 16;" :: "r"(dst), "l"(src));
}
#define CP_COMMIT()  asm volatile("cp.async.commit_group;" ::: "memory")
#define CP_WAIT(n)   asm volatile("cp.async.wait_group %0;" :: "n"(n) : "memory")

__device__ __forceinline__ void ldsm4(uint32_t* r, uint32_t addr) {
    asm volatile("ldmatrix.sync.aligned.m8n8.x4.shared.b16 {%0,%1,%2,%3}, [%4];"
                 : "=r"(r[0]), "=r"(r[1]), "=r"(r[2]), "=r"(r[3]) : "r"(addr));
}
// fp16 MMA, fp32 accumulate
__device__ __forceinline__ void mma16816h(float* d, const uint32_t* a, const uint32_t* b) {
    asm volatile(
        "mma.sync.aligned.m16n8k16.row.col.f32.f16.f16.f32 "
        "{%0,%1,%2,%3}, {%4,%5,%6,%7}, {%8,%9}, {%0,%1,%2,%3};"
        : "+f"(d[0]), "+f"(d[1]), "+f"(d[2]), "+f"(d[3])
        : "r"(a[0]), "r"(a[1]), "r"(a[2]), "r"(a[3]), "r"(b[0]), "r"(b[1]));
}

// ---------------------------------------------------------------------------
// Conversions.
// conv_x: fp32 -> fp16 hi + fp16 lo (X / ao path).
// conv_w: fp32 -> single fp16 (weights; W rounding is the only GEMM error).
// ---------------------------------------------------------------------------
__global__ __launch_bounds__(256) void conv_x(const float* __restrict__ src)
{
    int i = blockIdx.x * 256 + threadIdx.x;
    float4 v = ((const float4*)src)[i];
    __half h0 = __float2half_rn(v.x);
    __half h1 = __float2half_rn(v.y);
    __half h2 = __float2half_rn(v.z);
    __half h3 = __float2half_rn(v.w);
    __half2* hp = (__half2*)g_xhi;
    __half2* lp = (__half2*)g_xlo;
    hp[i * 2]     = __halves2half2(h0, h1);
    hp[i * 2 + 1] = __halves2half2(h2, h3);
    lp[i * 2]     = __halves2half2(__float2half_rn(v.x - __half2float(h0)),
                                   __float2half_rn(v.y - __half2float(h1)));
    lp[i * 2 + 1] = __halves2half2(__float2half_rn(v.z - __half2float(h2)),
                                   __float2half_rn(v.w - __half2float(h3)));
}

__global__ __launch_bounds__(256) void conv_w(
    const float* __restrict__ w0, const float* __restrict__ w1,
    const float* __restrict__ w2, const float* __restrict__ w3)
{
    int z = blockIdx.y;
    const float* src = z == 0 ? w0 : (z == 1 ? w1 : (z == 2 ? w2 : w3));
    int i = blockIdx.x * 256 + threadIdx.x;
    float4 v = ((const float4*)src)[i];
    __half2* hp = (__half2*)(g_wh + (size_t)z * 1048576);
    hp[i * 2]     = __halves2half2(__float2half_rn(v.x), __float2half_rn(v.y));
    hp[i * 2 + 1] = __halves2half2(__float2half_rn(v.z), __float2half_rn(v.w));
}

// ---------------------------------------------------------------------------
// Tensor-core GEMM (NT) via fp16 2-term split:
// Y = (Xhi + Xlo) @ Wh^T + bias.  grid (4, 128, nz); z selects W/bias/dst.
// 128x256 block, K-chunk 32, 512 threads (16 warps, 64x32 warp tile),
// 3-stage cp.async pipeline (40KB/stage = Ahi|Alo|B).
// ---------------------------------------------------------------------------
#define A_TILE_B 10240     // 128 rows * 80 bytes
#define B_TILE_B 20480     // 256 rows * 80 bytes
#define STAGE_B  40960     // Ahi|Alo|B
#define NSTAGE   3
__global__ __launch_bounds__(512, 1) void gemm_mma(
    int xsel, int wsel_base,
    const float* __restrict__ bias0, const float* __restrict__ bias1,
    const float* __restrict__ bias2,
    float* __restrict__ Yext, int ysel_base)
{
    const int z = blockIdx.z;
    const int wsel = wsel_base + z;
    const float* bias = z == 0 ? bias0 : (z == 1 ? bias1 : bias2);
    const __half* Xhi = xsel ? g_aohi : g_xhi;
    const __half* Xlo = xsel ? g_aolo : g_xlo;
    const __half* Wh  = g_wh + (size_t)wsel * 1048576;
    float* Y = (ysel_base < 0) ? Yext : sel_buf(ysel_base + z);

    extern __shared__ char smem[];
    const uint32_t sbase = smem_u32(smem);
    const int tid = threadIdx.x;
    const int lane = tid & 31, wid = tid >> 5;   // 16 warps
    const int wm = wid & 1, wn = wid >> 1;        // 2 x 8 warp grid, 64x32 tile
    const int m0 = blockIdx.y * 128, n0 = blockIdx.x * 256;

    float acc[4][4][4];
#pragma unroll
    for (int a = 0; a < 4; a++)
#pragma unroll
        for (int b = 0; b < 4; b++)
#pragma unroll
            for (int c = 0; c < 4; c++) acc[a][b][c] = 0.f;

    // chunk loader: 2048 x 16B segments, 4 per thread
    auto issue_chunk = [&](int c) {
        if (c < 32) {
            const int k0 = c * 32;
            const uint32_t dstb = sbase + (uint32_t)(c % NSTAGE) * STAGE_B;
#pragma unroll
            for (int it = 0; it < 4; it++) {
                const int id = it * 512 + tid;
                const __half* src;
                uint32_t dst;
                if (id < 1024) {              // A tiles (hi, lo)
                    const int t = id >> 9;
                    const int r = (id & 511) >> 2, seg = id & 3;
                    src = (t ? Xlo : Xhi) + (size_t)(m0 + r) * 1024 + k0 + seg * 8;
                    dst = dstb + t * A_TILE_B + r * 80 + seg * 16;
                } else {                      // B tile (single)
                    const int id2 = id - 1024;
                    const int r = id2 >> 2, seg = id2 & 3;
                    src = Wh + (size_t)(n0 + r) * 1024 + k0 + seg * 8;
                    dst = dstb + 2 * A_TILE_B + r * 80 + seg * 16;
                }
                cpasync16(dst, src);
            }
        }
        CP_COMMIT();
    };

    issue_chunk(0);
    issue_chunk(1);
    for (int c = 0; c < 32; c++) {
        CP_WAIT(1);            // chunk c landed (groups retire in order)
        __syncthreads();       // all threads past reads of buf (c-1)%3
        issue_chunk(c + 2);    // writes (c+2)%3 == (c-1)%3; overlaps compute
        const uint32_t st = sbase + (uint32_t)(c % NSTAGE) * STAGE_B;
#pragma unroll
        for (int ks = 0; ks < 2; ks++) {
            const uint32_t arow = (uint32_t)(lane & 15);
            const uint32_t acol = (uint32_t)(ks * 16 + (lane >> 4) * 8) * 2;
            uint32_t ahi[4][4], alo[4][4];
#pragma unroll
            for (int mt = 0; mt < 4; mt++) {
                const uint32_t off = (uint32_t)(wm * 64 + mt * 16 + arow) * 80 + acol;
                ldsm4(ahi[mt], st + off);
                ldsm4(alo[mt], st + A_TILE_B + off);
            }
            const uint32_t brow = (uint32_t)(((lane >> 4) << 3) + (lane & 7));
            const uint32_t bcol = (uint32_t)(ks * 16 + ((lane >> 3) & 1) * 8) * 2;
            uint32_t bf[2][4];
#pragma unroll
            for (int nb = 0; nb < 2; nb++) {
                const uint32_t off = (uint32_t)(wn * 32 + nb * 16 + brow) * 80 + bcol;
                ldsm4(bf[nb], st + 2 * A_TILE_B + off);
            }
            // per-accumulator contribution order: hi then lo
#pragma unroll
            for (int mt = 0; mt < 4; mt++)
#pragma unroll
                for (int nt = 0; nt < 4; nt++)
                    mma16816h(acc[mt][nt], ahi[mt], &bf[nt >> 1][(nt & 1) * 2]);
#pragma unroll
            for (int mt = 0; mt < 4; mt++)
#pragma unroll
                for (int nt = 0; nt < 4; nt++)
                    mma16816h(acc[mt][nt], alo[mt], &bf[nt >> 1][(nt & 1) * 2]);
        }
    }

    const int mrow = lane >> 2, ncol = (lane & 3) * 2;
#pragma unroll
    for (int mt = 0; mt < 4; mt++)
#pragma unroll
        for (int nt = 0; nt < 4; nt++) {
            const int m = m0 + wm * 64 + mt * 16 + mrow;
            const int n = n0 + wn * 32 + nt * 8 + ncol;
            const float b0 = __ldg(&bias[n]), b1 = __ldg(&bias[n + 1]);
            float* y0 = Y + (size_t)m * 1024 + n;
            float* y1 = Y + (size_t)(m + 8) * 1024 + n;
            *(float2*)y0 = make_float2(acc[mt][nt][0] + b0, acc[mt][nt][1] + b1);
            *(float2*)y1 = make_float2(acc[mt][nt][2] + b0, acc[mt][nt][3] + b1);
        }
}

// ---------------------------------------------------------------------------
// feat_kv v3: 512 threads (16 warps), grid 1024 = 64 bh x 16 chunks (256 rows),
// tiles of 64 rows.  Thread owns 4e x 4d -> 2 CTAs/SM, 50% occupancy.
// ---------------------------------------------------------------------------
#define FK_SMEM 82944
__global__ __launch_bounds__(512, 2) void feat_kv_kernel(const float* __restrict__ Pm)
{
    extern __shared__ float sm[];
    float (*Ps)[68]  = (float(*)[68])sm;
    float (*ks)[64]  = (float(*)[64])(sm + 4352);
    float (*vs)[64]  = (float(*)[64])(sm + 8448);
    float (*kf)[128] = (float(*)[128])(sm + 12544);

    const int tid = threadIdx.x, lane = tid & 31, warp = tid >> 5;
    const int bid = blockIdx.x;
    const int bh = bid >> 4, ch = bid & 15;
    const int b = bh >> 4, h = bh & 15;
    const size_t hb = (size_t)(b * N_) * E_ + h * 64;
    const int row0 = ch * 256;

    for (int i = tid; i < 4096; i += 512) Ps[i >> 6][i & 63] = Pm[i];
    __syncthreads();

    const int eg = tid >> 4, dg = tid & 15;
    float acc[4][4];
#pragma unroll
    for (int i = 0; i < 4; i++)
#pragma unroll
        for (int j = 0; j < 4; j++) acc[i][j] = 0.f;

    for (int t0 = 0; t0 < 256; t0 += 64) {
#pragma unroll
        for (int j = 0; j < 4; j++) {
            const int rl = warp * 4 + j;
            const int row = row0 + t0 + rl;
            const float* kr = g_k + hb + (size_t)row * E_;
            const float* vr = g_v + hb + (size_t)row * E_;
            float2 k2 = ((const float2*)kr)[lane];
            float2 v2 = ((const float2*)vr)[lane];
            ((float2*)vs[rl])[lane] = v2;
            float ss = k2.x * k2.x + k2.y * k2.y;
#pragma unroll
            for (int off = 16; off; off >>= 1) ss += __shfl_xor_sync(0xffffffffu, ss, off);
            float inv = 1.0f / (sqrtf(ss) + EPSN);
            ((float2*)ks[rl])[lane] = make_float2(k2.x * inv, k2.y * inv);
        }
        float p0[4], p1[4];
#pragma unroll
        for (int j = 0; j < 4; j++) { p0[j] = 0.f; p1[j] = 0.f; }
#pragma unroll
        for (int d4 = 0; d4 < 16; d4++) {
            float4 pa = *(const float4*)&Ps[lane][d4 * 4];
            float4 pb = *(const float4*)&Ps[lane + 32][d4 * 4];
#pragma unroll
            for (int j = 0; j < 4; j++) {
                float4 kk = *(const float4*)&ks[warp * 4 + j][d4 * 4];
                p0[j] += kk.x*pa.x + kk.y*pa.y + kk.z*pa.z + kk.w*pa.w;
                p1[j] += kk.x*pb.x + kk.y*pb.y + kk.z*pb.z + kk.w*pb.w;
            }
        }
#pragma unroll
        for (int j = 0; j < 4; j++) {
            const int rl = warp * 4 + j;
            float s0, c0, s1, c1;
            __sincosf(p0[j] * SCALE, &s0, &c0);
            __sincosf(p1[j] * SCALE, &s1, &c1);
            kf[rl][lane]      = s0 * FSCALE;
            kf[rl][lane + 32] = s1 * FSCALE;
            kf[rl][64 + lane] = c0 * FSCALE;
            kf[rl][96 + lane] = c1 * FSCALE;
        }
        __syncthreads();
#pragma unroll 8
        for (int r = 0; r < 64; r++) {
            float4 v4 = *(const float4*)&vs[r][dg * 4];
            float4 f4 = *(const float4*)&kf[r][eg * 4];
            float fa[4] = {f4.x, f4.y, f4.z, f4.w};
#pragma unroll
            for (int i = 0; i < 4; i++) {
                acc[i][0] = fmaf(fa[i], v4.x, acc[i][0]);
                acc[i][1] = fmaf(fa[i], v4.y, acc[i][1]);
                acc[i][2] = fmaf(fa[i], v4.z, acc[i][2]);
                acc[i][3] = fmaf(fa[i], v4.w, acc[i][3]);
            }
        }
        __syncthreads();
    }

    float* outp = g_kvp + (size_t)bid * 8192;
#pragma unroll
    for (int i = 0; i < 4; i++)
        *(float4*)(outp + (eg * 4 + i) * 64 + dg * 4) =
            make_float4(acc[i][0], acc[i][1], acc[i][2], acc[i][3]);
}

// ---------------------------------------------------------------------------
__global__ __launch_bounds__(256) void kv_reduce_kernel()
{
    int bh = blockIdx.x, tid = threadIdx.x;
    const float4* src = (const float4*)(g_kvp + (size_t)bh * 16 * 8192);
    float4* dst = (float4*)(g_kv + (size_t)bh * 8192);
    for (int i = tid; i < 2048; i += 256) {
        float4 s = src[i];
#pragma unroll
        for (int c = 1; c < 16; c++) {
            float4 t = src[c * 2048 + i];
            s.x += t.x; s.y += t.y; s.z += t.z; s.w += t.w;
        }
        dst[i] = s;
    }
}

// ---------------------------------------------------------------------------
// o_feat v4: 512 threads (16 warps), grid 1024; writes ao fp16 hi/lo splits.
// ---------------------------------------------------------------------------
#define OF_SMEM 100352
__global__ __launch_bounds__(512, 2) void o_feat_kernel(const float* __restrict__ Pm)
{
    extern __shared__ float sm[];
    float (*Ps)[68]   = (float(*)[68])sm;
    float (*kvt)[132] = (float(*)[132])(sm + 4352);
    float (*qs)[64]   = (float(*)[64])(sm + 12800);
    float (*qf)[128]  = (float(*)[128])(sm + 16896);

    const int tid = threadIdx.x, lane = tid & 31, warp = tid >> 5;
    const int bid = blockIdx.x;
    const int bh = bid >> 4, ch = bid & 15;
    const int b = bh >> 4, h = bh & 15;
    const size_t hb = (size_t)(b * N_) * E_ + h * 64;
    const int row0 = ch * 256;

    for (int i = tid; i < 4096; i += 512) Ps[i >> 6][i & 63] = Pm[i];
    {
        const float* kvg = g_kv + (size_t)bh * 8192;
        for (int i = tid; i < 8192; i += 512) kvt[i & 63][i >> 6] = kvg[i];
    }
    __syncthreads();

    for (int t0 = 0; t0 < 256; t0 += 64) {
#pragma unroll
        for (int j = 0; j < 4; j++) {
            const int rl = warp * 4 + j;
            const int row = row0 + t0 + rl;
            const float* qr = g_q + hb + (size_t)row * E_;
            float2 q2 = ((const float2*)qr)[lane];
            float ss = q2.x * q2.x + q2.y * q2.y;
#pragma unroll
            for (int off = 16; off; off >>= 1) ss += __shfl_xor_sync(0xffffffffu, ss, off);
            float inv = 1.0f / (sqrtf(ss) + EPSN);
            ((float2*)qs[rl])[lane] = make_float2(q2.x * inv, q2.y * inv);
        }
        float p0[4], p1[4];
#pragma unroll
        for (int j = 0; j < 4; j++) { p0[j] = 0.f; p1[j] = 0.f; }
#pragma unroll
        for (int d4 = 0; d4 < 16; d4++) {
            float4 pa = *(const float4*)&Ps[lane][d4 * 4];
            float4 pb = *(const float4*)&Ps[lane + 32][d4 * 4];
#pragma unroll
            for (int j = 0; j < 4; j++) {
                float4 kk = *(const float4*)&qs[warp * 4 + j][d4 * 4];
                p0[j] += kk.x*pa.x + kk.y*pa.y + kk.z*pa.z + kk.w*pa.w;
                p1[j] += kk.x*pb.x + kk.y*pb.y + kk.z*pb.z + kk.w*pb.w;
            }
        }
#pragma unroll
        for (int j = 0; j < 4; j++) {
            const int rl = warp * 4 + j;
            float s0, c0, s1, c1;
            __sincosf(p0[j] * SCALE, &s0, &c0);
            __sincosf(p1[j] * SCALE, &s1, &c1);
            qf[rl][lane]      = s0 * FSCALE;
            qf[rl][lane + 32] = s1 * FSCALE;
            qf[rl][64 + lane] = c0 * FSCALE;
            qf[rl][96 + lane] = c1 * FSCALE;
        }
        __syncthreads();
        float o0[4], o1[4];
#pragma unroll
        for (int j = 0; j < 4; j++) { o0[j] = 0.f; o1[j] = 0.f; }
#pragma unroll
        for (int e4 = 0; e4 < 32; e4++) {
            float4 kv0 = *(const float4*)&kvt[lane][e4 * 4];
            float4 kv1 = *(const float4*)&kvt[lane + 32][e4 * 4];
#pragma unroll
            for (int j = 0; j < 4; j++) {
                float4 q4 = *(const float4*)&qf[warp * 4 + j][e4 * 4];
                o0[j] += q4.x*kv0.x + q4.y*kv0.y + q4.z*kv0.z + q4.w*kv0.w;
                o1[j] += q4.x*kv1.x + q4.y*kv1.y + q4.z*kv1.z + q4.w*kv1.w;
            }
        }
#pragma unroll
        for (int j = 0; j < 4; j++) {
            const int row = row0 + t0 + warp * 4 + j;
            const size_t idx = hb + (size_t)row * E_ + lane;
            __half h0 = __float2half_rn(o0[j]);
            __half h1 = __float2half_rn(o1[j]);
            g_aohi[idx]      = h0;
            g_aohi[idx + 32] = h1;
            g_aolo[idx]      = __float2half_rn(o0[j] - __half2float(h0));
            g_aolo[idx + 32] = __float2half_rn(o1[j] - __half2float(h1));
        }
        __syncthreads();
    }
}

// ---------------------------------------------------------------------------
extern "C" void kernel_launch(void* const* d_in, const int* in_sizes, int n_in,
                              void* d_out, int out_size)
{
    const float* x  = (const float*)d_in[0];
    const float* Wq = (const float*)d_in[1];
    const float* bq = (const float*)d_in[2];
    const float* Wk = (const float*)d_in[3];
    const float* bk = (const float*)d_in[4];
    const float* Wv = (const float*)d_in[5];
    const float* bv = (const float*)d_in[6];
    const float* Wo = (const float*)d_in[7];
    const float* bo = (const float*)d_in[8];
    const float* P  = (const float*)d_in[9];
    float* out = (float*)d_out;

    cudaFuncSetAttribute(gemm_mma,
                         cudaFuncAttributeMaxDynamicSharedMemorySize, NSTAGE * STAGE_B);
    cudaFuncSetAttribute(feat_kv_kernel,
                         cudaFuncAttributeMaxDynamicSharedMemorySize, FK_SMEM);
    cudaFuncSetAttribute(o_feat_kernel,
                         cudaFuncAttributeMaxDynamicSharedMemorySize, OF_SMEM);

    conv_x<<<16384, 256>>>(x);
    conv_w<<<dim3(1024, 4), 256>>>(Wq, Wk, Wv, Wo);

    // fused q/k/v projections (fp16 2-term split GEMM)
    gemm_mma<<<dim3(4, 128, 3), 512, NSTAGE * STAGE_B>>>(
        0, 0, bq, bk, bv, nullptr, 0);

    feat_kv_kernel<<<1024, 512, FK_SMEM>>>(P);
    kv_reduce_kernel<<<64, 256>>>();
    o_feat_kernel<<<1024, 512, OF_SMEM>>>(P);     // -> g_aohi/g_aolo

    // output projection
    gemm_mma<<<dim3(4, 128, 1), 512, NSTAGE * STAGE_B>>>(
        1, 3, bo, bo, bo, out, -1);
}